// round 4
// baseline (speedup 1.0000x reference)
#include <cuda_runtime.h>
#include <math.h>

// ---------------- static scratch ----------------
__device__ __align__(256) float g_EMB[512*64*256];
__device__ __align__(256) float g_XA [512*64*512];
__device__ __align__(256) float g_XB [512*64*512];
__device__ __align__(256) float g_GT [512*64*2048];
__device__ __align__(256) float g_T0 [512*64*256];
__device__ __align__(256) float g_T1 [512*64*256];
__device__ __align__(256) float g_P0 [512*64*256];
__device__ __align__(256) float g_P1 [512*64*256];
__device__ __align__(256) float g_H  [2*2*256*64];   // [pp][dir][k][b]
__device__ __align__(256) float g_FU [64*774];
__device__ __align__(256) float g_S1 [64*512];
__device__ __align__(256) float g_S2 [64*256];
__device__ unsigned g_barG[256];                     // 8 groups, padded

// ---------------- helpers ----------------
__device__ __forceinline__ unsigned long long pk2(float lo, float hi){
    unsigned long long u; asm("mov.b64 %0,{%1,%2};":"=l"(u):"f"(lo),"f"(hi)); return u;
}
__device__ __forceinline__ void fma2(unsigned long long&d,unsigned long long a,unsigned long long b){
    asm("fma.rn.f32x2 %0,%1,%2,%0;":"+l"(d):"l"(a),"l"(b));
}
__device__ __forceinline__ void upk2(unsigned long long u,float&lo,float&hi){
    asm("mov.b64 {%0,%1},%2;":"=f"(lo),"=f"(hi):"l"(u));
}
__device__ __forceinline__ float sigm(float x){ return 1.f/(1.f+__expf(-x)); }

// ---------------- embedding gather ----------------
__global__ void k_embed(const int* __restrict__ seq, const float* __restrict__ tab){
    int m = blockIdx.x; int s = m>>6, b = m&63;
    long tok = seq[b*512+s];
    const float4* src = (const float4*)(tab + tok*256);
    ((float4*)(g_EMB + (long)m*256))[threadIdx.x] = src[threadIdx.x];
}

__global__ void k_rst(){ g_barG[threadIdx.x] = 0u; }

// ---------------- GEMM: C[M,N] = A[M,K] @ W[N,K]^T + bias ----------------
// 128x128 tile, 256 threads, 8x8 micro-tile, f32x2 over N. K % 16 == 0.
__global__ void __launch_bounds__(256,2) k_gemm(const float* __restrict__ A,
        const float* __restrict__ W, const float* __restrict__ bias,
        float* __restrict__ C, int K, int N){
    __shared__ float As[16][128];
    __shared__ float Bs[16][128];
    int tid = threadIdx.x;
    int m0 = blockIdx.y*128, n0 = blockIdx.x*128;
    int lr = tid>>1, lk = (tid&1)*8;
    const float* Ag = A + (long)(m0+lr)*K + lk;
    const float* Wg = W + (long)(n0+lr)*K + lk;
    int tx = tid&15, ty = tid>>4;
    unsigned long long acc[8][4];
#pragma unroll
    for(int i=0;i<8;i++){ acc[i][0]=0ULL; acc[i][1]=0ULL; acc[i][2]=0ULL; acc[i][3]=0ULL; }
    float4 pa0 = *(const float4*)Ag,     pa1 = *(const float4*)(Ag+4);
    float4 pb0 = *(const float4*)Wg,     pb1 = *(const float4*)(Wg+4);
    for(int kt=0; kt<K; kt+=16){
        As[lk+0][lr]=pa0.x; As[lk+1][lr]=pa0.y; As[lk+2][lr]=pa0.z; As[lk+3][lr]=pa0.w;
        As[lk+4][lr]=pa1.x; As[lk+5][lr]=pa1.y; As[lk+6][lr]=pa1.z; As[lk+7][lr]=pa1.w;
        Bs[lk+0][lr]=pb0.x; Bs[lk+1][lr]=pb0.y; Bs[lk+2][lr]=pb0.z; Bs[lk+3][lr]=pb0.w;
        Bs[lk+4][lr]=pb1.x; Bs[lk+5][lr]=pb1.y; Bs[lk+6][lr]=pb1.z; Bs[lk+7][lr]=pb1.w;
        __syncthreads();
        if(kt+16<K){
            const float* An = Ag + kt + 16;
            const float* Wn = Wg + kt + 16;
            pa0 = *(const float4*)An;     pa1 = *(const float4*)(An+4);
            pb0 = *(const float4*)Wn;     pb1 = *(const float4*)(Wn+4);
        }
#pragma unroll
        for(int k=0;k<16;k++){
            float4 a0 = *(const float4*)&As[k][ty*8];
            float4 a1 = *(const float4*)&As[k][ty*8+4];
            ulonglong2 b0 = *(const ulonglong2*)&Bs[k][tx*8];
            ulonglong2 b1 = *(const ulonglong2*)&Bs[k][tx*8+4];
            float av[8] = {a0.x,a0.y,a0.z,a0.w,a1.x,a1.y,a1.z,a1.w};
#pragma unroll
            for(int i=0;i<8;i++){
                unsigned long long w2 = pk2(av[i],av[i]);
                fma2(acc[i][0],w2,b0.x); fma2(acc[i][1],w2,b0.y);
                fma2(acc[i][2],w2,b1.x); fma2(acc[i][3],w2,b1.y);
            }
        }
        __syncthreads();
    }
    float bv[8];
#pragma unroll
    for(int j=0;j<8;j++) bv[j] = bias[n0+tx*8+j];
#pragma unroll
    for(int i=0;i<8;i++){
        float x0,x1,x2,x3,x4,x5,x6,x7;
        upk2(acc[i][0],x0,x1); upk2(acc[i][1],x2,x3);
        upk2(acc[i][2],x4,x5); upk2(acc[i][3],x6,x7);
        long m = m0 + ty*8 + i;
        *(float4*)(C + m*N + n0 + tx*8)     = make_float4(x0+bv[0],x1+bv[1],x2+bv[2],x3+bv[3]);
        *(float4*)(C + m*N + n0 + tx*8 + 4) = make_float4(x4+bv[4],x5+bv[5],x6+bv[6],x7+bv[7]);
    }
}

// ---------------- persistent bidirectional LSTM layer ----------------
// 128 CTAs: dir(2) x hidden-block(16, 16 units) x batch-group(4, 16 b).
// Whh slice in registers (k split over q=tid>>6). Barrier per (dir,bg) group of 16.
#define LSM ((256*16 + 4*64*16 + 64*16)*4)

__global__ void __launch_bounds__(256) k_lstm(const float* __restrict__ gates,
        const float* __restrict__ WhhA, const float* __restrict__ WhhB,
        float* __restrict__ out){
    extern __shared__ float sm[];
    float* hsh = sm;                 // [256][16]
    float* ps  = sm + 256*16;        // [4][64][16]
    float* gsh = ps + 4*64*16;       // [64][16]
    int tid = threadIdx.x, bid = blockIdx.x;
    int dir = bid>>6, hb = (bid>>2)&15, bg = bid&3;
    int hu0 = hb*16, b0 = bg*16;
    unsigned* ctr = &g_barG[(dir*4+bg)*32];
    const float* Whh = dir ? WhhB : WhhA;
    int r = tid&63, q = tid>>6;
    int gate = r>>4, u = r&15;
    // Whh row (gate*256+hu0+u), k-range [q*64, q*64+64) -> registers
    float wreg[64];
    const float* wsrc = Whh + (long)(gate*256+hu0+u)*256 + q*64;
#pragma unroll
    for(int j=0;j<16;j++) *(float4*)&wreg[j*4] = *(const float4*)(wsrc + j*4);
    int cu = tid>>4, cb = tid&15;    // gate-combine mapping
    float creg = 0.f;
    // zero-init h (own slice), arrive, wait for group
    g_H[((long)(0*2+dir)*256 + hu0+cu)*64 + b0+cb] = 0.f;
    __syncthreads();
    unsigned tc = 16;
    if(tid==0){
        __threadfence(); atomicAdd(ctr,1u);
        while(*(volatile unsigned*)ctr < tc) __nanosleep(32);
        __threadfence();
    }
    __syncthreads();
    const float* hq = hsh + q*64*16;
    for(int si=0; si<512; si++){
        int s = dir ? 511-si : si;
        int pp = si&1;
        // gate prefetch (independent of barrier/h)
        long gb = ((long)s*64 + b0+cb)*2048 + dir*1024 + hu0 + cu;
        float xi = __ldg(gates+gb),     xf = __ldg(gates+gb+256);
        float xg = __ldg(gates+gb+512), xo = __ldg(gates+gb+768);
        // stage h[pp] into smem
        for(int i=tid;i<1024;i+=256){
            int k=i>>2, c4=i&3;
            float4 v = __ldcg(((const float4*)(g_H + (((long)pp*2+dir)*256+k)*64 + b0)) + c4);
            *(float4*)(hsh + k*16 + c4*4) = v;
        }
        __syncthreads();
        // partial dot over k-quarter
        unsigned long long a0=0,a1=0,a2=0,a3=0,a4=0,a5=0,a6=0,a7=0;
#pragma unroll
        for(int j=0;j<64;j++){
            unsigned long long w2 = pk2(wreg[j],wreg[j]);
            const ulonglong2* hp = (const ulonglong2*)(hq + j*16);
            ulonglong2 hA=hp[0], hB=hp[1], hC=hp[2], hD=hp[3];
            fma2(a0,w2,hA.x); fma2(a1,w2,hA.y); fma2(a2,w2,hB.x); fma2(a3,w2,hB.y);
            fma2(a4,w2,hC.x); fma2(a5,w2,hC.y); fma2(a6,w2,hD.x); fma2(a7,w2,hD.y);
        }
        unsigned long long* pr = (unsigned long long*)(ps + ((long)q*64 + r)*16);
        pr[0]=a0; pr[1]=a1; pr[2]=a2; pr[3]=a3; pr[4]=a4; pr[5]=a5; pr[6]=a6; pr[7]=a7;
        __syncthreads();
        // reduce partials across q
        {
            int rr = tid>>2, c4 = (tid&3)*4;
            float4 v0 = *(const float4*)(ps + (0*64+rr)*16 + c4);
            float4 v1 = *(const float4*)(ps + (1*64+rr)*16 + c4);
            float4 v2 = *(const float4*)(ps + (2*64+rr)*16 + c4);
            float4 v3 = *(const float4*)(ps + (3*64+rr)*16 + c4);
            float4 o; o.x=v0.x+v1.x+v2.x+v3.x; o.y=v0.y+v1.y+v2.y+v3.y;
            o.z=v0.z+v1.z+v2.z+v3.z; o.w=v0.w+v1.w+v2.w+v3.w;
            *(float4*)(gsh + rr*16 + c4) = o;
        }
        __syncthreads();
        // gate combine
        float gi = gsh[(   cu)*16+cb] + xi;
        float gf = gsh[(16+cu)*16+cb] + xf;
        float gg = gsh[(32+cu)*16+cb] + xg;
        float go = gsh[(48+cu)*16+cb] + xo;
        creg = sigm(gf)*creg + sigm(gi)*tanhf(gg);
        float h = sigm(go)*tanhf(creg);
        __stcg(g_H + (((long)(1-pp)*2+dir)*256 + hu0+cu)*64 + b0+cb, h);
        out[((long)s*64 + b0+cb)*512 + dir*256 + hu0+cu] = h;
        __syncthreads();
        tc += 16;
        if(tid==0){
            __threadfence(); atomicAdd(ctr,1u);
            while(*(volatile unsigned*)ctr < tc) __nanosleep(32);
            __threadfence();
        }
        __syncthreads();
    }
}

// ---------------- GCN banded adjacency ----------------
__global__ void k_band(const float* __restrict__ x, const float* __restrict__ mask,
                       float* __restrict__ o){
    int m = blockIdx.x; int s=m>>6, b=m&63;
    float mm = mask[b*512+s];
    float mn = (s<511)? mask[b*512+s+1] : 0.f;
    float mp = (s>0)?   mask[b*512+s-1] : 0.f;
    float rs = mm*(mp+mn)+1e-8f;
    float cn = mm*mn/rs, cp = mm*mp/rs;
    int t = threadIdx.x;
    float4 vn = (s<511)? ((const float4*)(x+((long)m+64)*256))[t] : make_float4(0,0,0,0);
    float4 vp = (s>0)?   ((const float4*)(x+((long)m-64)*256))[t] : make_float4(0,0,0,0);
    float4 r; r.x=cn*vn.x+cp*vp.x; r.y=cn*vn.y+cp*vp.y;
    r.z=cn*vn.z+cp*vp.z; r.w=cn*vn.w+cp*vp.w;
    ((float4*)(o+(long)m*256))[t]=r;
}

// ---------------- residual + LayerNorm + ReLU ----------------
__global__ void k_ln(const float* __restrict__ go, const float* __restrict__ xin,
                     const float* __restrict__ gamma, const float* __restrict__ beta,
                     float* __restrict__ o){
    __shared__ float rs1[8], rs2[8];
    long m = blockIdx.x; int t = threadIdx.x;
    float v = go[m*256+t] + xin[m*256+t];
    float s1=v, s2=v*v;
#pragma unroll
    for(int w=16;w;w>>=1){ s1+=__shfl_xor_sync(~0u,s1,w); s2+=__shfl_xor_sync(~0u,s2,w); }
    if((t&31)==0){ rs1[t>>5]=s1; rs2[t>>5]=s2; }
    __syncthreads();
    float S1=0,S2=0;
#pragma unroll
    for(int i=0;i<8;i++){ S1+=rs1[i]; S2+=rs2[i]; }
    float mu=S1*(1.f/256.f), var=S2*(1.f/256.f)-mu*mu;
    float inv=rsqrtf(var+1e-5f);
    float y=(v-mu)*inv*gamma[t]+beta[t];
    o[m*256+t]=fmaxf(y,0.f);
}

// ---------------- masked mean pooling + fuse ----------------
__global__ void k_pool(const float* __restrict__ lstm, const float* __restrict__ gcn,
                       const float* __restrict__ mask, const float* __restrict__ aux){
    int b = blockIdx.x, t = threadIdx.x;
    float dn=0.f;
    for(int s=0;s<512;s++) dn += mask[b*512+s];
    dn = fmaxf(dn,1e-8f);
    float acc=0.f;
    for(int s=0;s<512;s++) acc += lstm[((long)s*64+b)*512+t]*mask[b*512+s];
    g_FU[b*774+t]=acc/dn;
    if(t<256){
        float a2=0.f;
        for(int s=0;s<512;s++) a2 += gcn[((long)s*64+b)*256+t]*mask[b*512+s];
        g_FU[b*774+512+t]=a2/dn;
    }
    if(t<6) g_FU[b*774+768+t]=aux[b*6+t];
}

// ---------------- small FC ----------------
__global__ void k_fc(const float* __restrict__ in, const float* __restrict__ W,
                     const float* __restrict__ bias, float* __restrict__ o,
                     int K, int N, int relu){
    int idx = blockIdx.x*blockDim.x + threadIdx.x;
    if(idx >= 64*N) return;
    int b = idx/N, n = idx%N;
    const float* ip = in + (long)b*K;
    const float* wp = W + (long)n*K;
    float a=0.f;
    for(int k=0;k<K;k++) a += ip[k]*wp[k];
    a += bias[n];
    o[idx] = relu ? fmaxf(a,0.f) : a;
}

// ---------------- launch ----------------
extern "C" void kernel_launch(void* const* d_in, const int* in_sizes, int n_in,
                              void* d_out, int out_size){
    const int*   seq  = (const int*)  d_in[0];
    const float* mask = (const float*)d_in[1];
    const float* aux  = (const float*)d_in[2];
    const float* emb  = (const float*)d_in[3];
    const float* Wih0 = (const float*)d_in[4];
    const float* Whh0 = (const float*)d_in[5];
    const float* b0   = (const float*)d_in[6];
    const float* WihL = (const float*)d_in[7];
    const float* WhhL = (const float*)d_in[8];
    const float* bLp  = (const float*)d_in[9];
    const float* gW   = (const float*)d_in[10];
    const float* gb   = (const float*)d_in[11];
    const float* gga  = (const float*)d_in[12];
    const float* gbe  = (const float*)d_in[13];
    const float* f1W  = (const float*)d_in[14];
    const float* f1b  = (const float*)d_in[15];
    const float* f2W  = (const float*)d_in[16];
    const float* f2b  = (const float*)d_in[17];
    const float* h0W  = (const float*)d_in[18];
    const float* h0b  = (const float*)d_in[19];
    const float* h1W  = (const float*)d_in[20];
    const float* h1b  = (const float*)d_in[21];
    float* out = (float*)d_out;

    float *pEMB,*pXA,*pXB,*pGT,*pT0,*pT1,*pP0,*pP1,*pFU,*pS1,*pS2;
    cudaGetSymbolAddress((void**)&pEMB,g_EMB);
    cudaGetSymbolAddress((void**)&pXA, g_XA);
    cudaGetSymbolAddress((void**)&pXB, g_XB);
    cudaGetSymbolAddress((void**)&pGT, g_GT);
    cudaGetSymbolAddress((void**)&pT0, g_T0);
    cudaGetSymbolAddress((void**)&pT1, g_T1);
    cudaGetSymbolAddress((void**)&pP0, g_P0);
    cudaGetSymbolAddress((void**)&pP1, g_P1);
    cudaGetSymbolAddress((void**)&pFU, g_FU);
    cudaGetSymbolAddress((void**)&pS1, g_S1);
    cudaGetSymbolAddress((void**)&pS2, g_S2);
    cudaFuncSetAttribute(k_lstm, cudaFuncAttributeMaxDynamicSharedMemorySize, LSM);

    k_embed<<<32768,64>>>(seq, emb);

    const float* inp = pEMB; int K = 256;
    float* lo = pXA;
    for(int l=0;l<5;l++){
        const float* wih = l ? WihL + (long)(l-1)*2*1024*512 : Wih0;
        const float* whh = l ? WhhL + (long)(l-1)*2*1024*256 : Whh0;
        const float* bb  = l ? bLp  + (long)(l-1)*2*1024      : b0;
        dim3 gg(2048/128, 32768/128);
        k_gemm<<<gg,256>>>(inp, wih, bb, pGT, K, 2048);
        k_rst<<<1,256>>>();
        lo = (l&1) ? pXB : pXA;
        k_lstm<<<128,256,LSM>>>(pGT, whh, whh + 1024*256, lo);
        inp = lo; K = 512;
    }
    const float* lstmOut = lo;

    const float* gin = pEMB;
    float* gout = pP0;
    for(int i=0;i<3;i++){
        k_band<<<32768,64>>>(gin, mask, pT0);
        dim3 gg(256/128, 32768/128);
        k_gemm<<<gg,256>>>(pT0, gW + (long)i*256*256, gb + i*256, pT1, 256, 256);
        gout = (i&1) ? pP1 : pP0;
        k_ln<<<32768,256>>>(pT1, gin, gga + i*256, gbe + i*256, gout);
        gin = gout;
    }

    k_pool<<<64,512>>>(lstmOut, gout, mask, aux);
    k_fc<<<(64*512+255)/256,256>>>(pFU, f1W, f1b, pS1, 774, 512, 1);
    k_fc<<<(64*256+255)/256,256>>>(pS1, f2W, f2b, pS2, 512, 256, 1);
    k_fc<<<(64*10+255)/256,256>>>(pS2, h0W, h0b, out,      256, 10, 0);
    k_fc<<<(64*5 +255)/256,256>>>(pS2, h1W, h1b, out+640, 256,  5, 0);
}

// round 5
// speedup vs baseline: 1.0704x; 1.0704x over previous
#include <cuda_runtime.h>
#include <math.h>

// ---------------- static scratch ----------------
__device__ __align__(256) float g_EMB[512*64*256];
__device__ __align__(256) float g_XA [512*64*512];
__device__ __align__(256) float g_XB [512*64*512];
__device__ __align__(256) float g_GT [512*64*2048];
__device__ __align__(256) float g_T0 [512*64*256];
__device__ __align__(256) float g_T1 [512*64*256];
__device__ __align__(256) float g_P0 [512*64*256];
__device__ __align__(256) float g_P1 [512*64*256];
__device__ __align__(256) float g_H  [2*2*256*64];   // [pp][dir][k][b]
__device__ __align__(256) float g_FU [64*774];
__device__ __align__(256) float g_S1 [64*512];
__device__ __align__(256) float g_S2 [64*256];

// ---------------- helpers ----------------
__device__ __forceinline__ unsigned long long pk2(float lo, float hi){
    unsigned long long u; asm("mov.b64 %0,{%1,%2};":"=l"(u):"f"(lo),"f"(hi)); return u;
}
__device__ __forceinline__ void fma2(unsigned long long&d,unsigned long long a,unsigned long long b){
    asm("fma.rn.f32x2 %0,%1,%2,%0;":"+l"(d):"l"(a),"l"(b));
}
__device__ __forceinline__ void upk2(unsigned long long u,float&lo,float&hi){
    asm("mov.b64 {%0,%1},%2;":"=f"(lo),"=f"(hi):"l"(u));
}
__device__ __forceinline__ float sigm(float x){ return 1.f/(1.f+__expf(-x)); }

// ---------------- embedding gather ----------------
__global__ void k_embed(const int* __restrict__ seq, const float* __restrict__ tab){
    int m = blockIdx.x; int s = m>>6, b = m&63;
    long tok = seq[b*512+s];
    const float4* src = (const float4*)(tab + tok*256);
    ((float4*)(g_EMB + (long)m*256))[threadIdx.x] = src[threadIdx.x];
}

// ---------------- GEMM: C[M,N] = A[M,K] @ W[N,K]^T + bias ----------------
// 64x64 tile, 256 threads, 4x4 micro-tile, f32x2 over N. K % 16 == 0.
// (round-3 proven version, unchanged)
__global__ void __launch_bounds__(256) k_gemm(const float* __restrict__ A,
        const float* __restrict__ W, const float* __restrict__ bias,
        float* __restrict__ C, int K, int N){
    __shared__ float As[16][68];
    __shared__ float Bs[16][68];
    int tid = threadIdx.x;
    int m0 = blockIdx.y*64, n0 = blockIdx.x*64;
    int lr = tid>>2, lk = (tid&3)*4;
    const float* Ag = A + (long)(m0+lr)*K + lk;
    const float* Wg = W + (long)(n0+lr)*K + lk;
    int tx = tid&15, ty = tid>>4;
    unsigned long long acc[4][2];
#pragma unroll
    for(int i=0;i<4;i++){ acc[i][0]=0ULL; acc[i][1]=0ULL; }
    for(int kt=0; kt<K; kt+=16){
        float4 a4 = *(const float4*)(Ag+kt);
        float4 b4 = *(const float4*)(Wg+kt);
        As[lk+0][lr]=a4.x; As[lk+1][lr]=a4.y; As[lk+2][lr]=a4.z; As[lk+3][lr]=a4.w;
        Bs[lk+0][lr]=b4.x; Bs[lk+1][lr]=b4.y; Bs[lk+2][lr]=b4.z; Bs[lk+3][lr]=b4.w;
        __syncthreads();
#pragma unroll
        for(int k=0;k<16;k++){
            float4 av = *(const float4*)&As[k][ty*4];
            ulonglong2 bv = *(const ulonglong2*)&Bs[k][tx*4];
            unsigned long long a0=pk2(av.x,av.x), a1=pk2(av.y,av.y);
            unsigned long long a2=pk2(av.z,av.z), a3=pk2(av.w,av.w);
            fma2(acc[0][0],a0,bv.x); fma2(acc[0][1],a0,bv.y);
            fma2(acc[1][0],a1,bv.x); fma2(acc[1][1],a1,bv.y);
            fma2(acc[2][0],a2,bv.x); fma2(acc[2][1],a2,bv.y);
            fma2(acc[3][0],a3,bv.x); fma2(acc[3][1],a3,bv.y);
        }
        __syncthreads();
    }
    const float* bp = bias + n0 + tx*4;
    float b0v=bp[0], b1v=bp[1], b2v=bp[2], b3v=bp[3];
#pragma unroll
    for(int i=0;i<4;i++){
        float x0,x1,x2,x3; upk2(acc[i][0],x0,x1); upk2(acc[i][1],x2,x3);
        long m = m0 + ty*4 + i;
        *(float4*)(C + m*N + n0 + tx*4) = make_float4(x0+b0v,x1+b1v,x2+b2v,x3+b3v);
    }
}

// ---------------- persistent bidirectional LSTM layer (cluster barriers) ---
// 128 CTAs: dir(2) x batch-group(8 of 8) x hidden-block(8 of 32 units).
// Cluster of 8 = the hidden-block dim for one (dir,bg): h exchanged via L2,
// synchronized with hardware barrier.cluster (release/acquire). No global state.
#define LSM ((128*257 + 2048 + 2048 + 1024)*4)

__global__ void __launch_bounds__(256,1) __cluster_dims__(8,1,1)
k_lstm(const float* __restrict__ gates, const float* __restrict__ WhhA,
       const float* __restrict__ WhhB, float* __restrict__ out){
    extern __shared__ float sm[];
    float* Wsh = sm;                  // [128][257]
    float* hsh = sm + 128*257;        // [256 k][8 b]
    float* ps  = hsh + 2048;          // [2 q][128 r][8 b]
    float* gsh = ps + 2048;           // [128 r][8 b]
    int tid = threadIdx.x, bid = blockIdx.x;
    int dir = bid>>6, bg = (bid>>3)&7, hb = bid&7;
    int hu0 = hb*32, b0 = bg*8;
    const float* Whh = dir ? WhhB : WhhA;
    // load Whh slice: local row (g*32+u) <- global row (g*256+hu0+u), 256 k each
    for(int i=tid;i<8192;i+=256){
        int lrw = i>>6, c4 = (i&63)*4;
        int g = lrw>>5, u = lrw&31;
        float4 v = *(const float4*)(Whh + (long)(g*256+hu0+u)*256 + c4);
        float* dst = &Wsh[lrw*257 + c4];
        dst[0]=v.x; dst[1]=v.y; dst[2]=v.z; dst[3]=v.w;
    }
    int r = tid&127, q = tid>>7;      // dot mapping
    int cu = tid>>3, cb = tid&7;      // combine mapping (32 units x 8 batch)
    float creg = 0.f;
    __stcg(&g_H[((long)(0*2+dir)*256 + hu0+cu)*64 + b0+cb], 0.f);
    __syncthreads();
    __threadfence();
    asm volatile("barrier.cluster.arrive.aligned;" ::: "memory");
    const float* wrow = Wsh + r*257 + q*128;
    int sk0 = tid>>1, skh = (tid&1)*4;
    for(int si=0; si<512; si++){
        int s = dir ? 511-si : si;
        int pp = si&1;
        // gate prefetch (independent of h — overlaps the barrier wait)
        long gb = ((long)s*64 + b0+cb)*2048 + dir*1024 + hu0 + cu;
        float xi = __ldg(gates+gb),     xf = __ldg(gates+gb+256);
        float xg = __ldg(gates+gb+512), xo = __ldg(gates+gb+768);
        asm volatile("barrier.cluster.wait.aligned;" ::: "memory");
        // stage h[pp] (full 256 units x 8 batch) into smem
        {
            long base = ((long)pp*2 + dir)*256;
            float4 v0 = __ldcg((const float4*)(g_H + (base + sk0      )*64 + b0 + skh));
            float4 v1 = __ldcg((const float4*)(g_H + (base + sk0 + 128)*64 + b0 + skh));
            *(float4*)&hsh[sk0*8 + skh]       = v0;
            *(float4*)&hsh[(sk0+128)*8 + skh] = v1;
        }
        __syncthreads();
        // partial dot: row r (gate*32+unit), k-half q, 8 batch
        unsigned long long a0=0,a1=0,a2=0,a3=0;
#pragma unroll 8
        for(int j=0;j<128;j++){
            float w = wrow[j];
            unsigned long long w2 = pk2(w,w);
            const ulonglong2* hp = (const ulonglong2*)&hsh[(q*128+j)*8];
            ulonglong2 h0 = hp[0], h1 = hp[1];
            fma2(a0,w2,h0.x); fma2(a1,w2,h0.y);
            fma2(a2,w2,h1.x); fma2(a3,w2,h1.y);
        }
        {
            unsigned long long* pr = (unsigned long long*)&ps[(q*128+r)*8];
            pr[0]=a0; pr[1]=a1; pr[2]=a2; pr[3]=a3;
        }
        __syncthreads();
        // reduce the two k-halves
        {
            int rr = tid>>1, hf = (tid&1)*4;
            float4 v0 = *(const float4*)&ps[rr*8 + hf];
            float4 v1 = *(const float4*)&ps[(128+rr)*8 + hf];
            *(float4*)&gsh[rr*8 + hf] =
                make_float4(v0.x+v1.x, v0.y+v1.y, v0.z+v1.z, v0.w+v1.w);
        }
        __syncthreads();
        // gate combine
        float gi = gsh[(    cu)*8+cb] + xi;
        float gf = gsh[(32+cu)*8+cb] + xf;
        float gg = gsh[(64+cu)*8+cb] + xg;
        float go = gsh[(96+cu)*8+cb] + xo;
        creg = sigm(gf)*creg + sigm(gi)*tanhf(gg);
        float h = sigm(go)*tanhf(creg);
        __stcg(&g_H[(((long)(1-pp)*2 + dir)*256 + hu0+cu)*64 + b0+cb], h);
        out[((long)s*64 + b0+cb)*512 + dir*256 + hu0+cu] = h;
        __threadfence();
        asm volatile("barrier.cluster.arrive.aligned;" ::: "memory");
    }
    asm volatile("barrier.cluster.wait.aligned;" ::: "memory");
}

// ---------------- GCN banded adjacency ----------------
__global__ void k_band(const float* __restrict__ x, const float* __restrict__ mask,
                       float* __restrict__ o){
    int m = blockIdx.x; int s=m>>6, b=m&63;
    float mm = mask[b*512+s];
    float mn = (s<511)? mask[b*512+s+1] : 0.f;
    float mp = (s>0)?   mask[b*512+s-1] : 0.f;
    float rs = mm*(mp+mn)+1e-8f;
    float cn = mm*mn/rs, cp = mm*mp/rs;
    int t = threadIdx.x;
    float4 vn = (s<511)? ((const float4*)(x+((long)m+64)*256))[t] : make_float4(0,0,0,0);
    float4 vp = (s>0)?   ((const float4*)(x+((long)m-64)*256))[t] : make_float4(0,0,0,0);
    float4 r; r.x=cn*vn.x+cp*vp.x; r.y=cn*vn.y+cp*vp.y;
    r.z=cn*vn.z+cp*vp.z; r.w=cn*vn.w+cp*vp.w;
    ((float4*)(o+(long)m*256))[t]=r;
}

// ---------------- residual + LayerNorm + ReLU ----------------
__global__ void k_ln(const float* __restrict__ go, const float* __restrict__ xin,
                     const float* __restrict__ gamma, const float* __restrict__ beta,
                     float* __restrict__ o){
    __shared__ float rs1[8], rs2[8];
    long m = blockIdx.x; int t = threadIdx.x;
    float v = go[m*256+t] + xin[m*256+t];
    float s1=v, s2=v*v;
#pragma unroll
    for(int w=16;w;w>>=1){ s1+=__shfl_xor_sync(~0u,s1,w); s2+=__shfl_xor_sync(~0u,s2,w); }
    if((t&31)==0){ rs1[t>>5]=s1; rs2[t>>5]=s2; }
    __syncthreads();
    float S1=0,S2=0;
#pragma unroll
    for(int i=0;i<8;i++){ S1+=rs1[i]; S2+=rs2[i]; }
    float mu=S1*(1.f/256.f), var=S2*(1.f/256.f)-mu*mu;
    float inv=rsqrtf(var+1e-5f);
    float y=(v-mu)*inv*gamma[t]+beta[t];
    o[m*256+t]=fmaxf(y,0.f);
}

// ---------------- masked mean pooling + fuse ----------------
__global__ void k_pool(const float* __restrict__ lstm, const float* __restrict__ gcn,
                       const float* __restrict__ mask, const float* __restrict__ aux){
    int b = blockIdx.x, t = threadIdx.x;
    float dn=0.f;
    for(int s=0;s<512;s++) dn += mask[b*512+s];
    dn = fmaxf(dn,1e-8f);
    float acc=0.f;
    for(int s=0;s<512;s++) acc += lstm[((long)s*64+b)*512+t]*mask[b*512+s];
    g_FU[b*774+t]=acc/dn;
    if(t<256){
        float a2=0.f;
        for(int s=0;s<512;s++) a2 += gcn[((long)s*64+b)*256+t]*mask[b*512+s];
        g_FU[b*774+512+t]=a2/dn;
    }
    if(t<6) g_FU[b*774+768+t]=aux[b*6+t];
}

// ---------------- small FC ----------------
__global__ void k_fc(const float* __restrict__ in, const float* __restrict__ W,
                     const float* __restrict__ bias, float* __restrict__ o,
                     int K, int N, int relu){
    int idx = blockIdx.x*blockDim.x + threadIdx.x;
    if(idx >= 64*N) return;
    int b = idx/N, n = idx%N;
    const float* ip = in + (long)b*K;
    const float* wp = W + (long)n*K;
    float a=0.f;
    for(int k=0;k<K;k++) a += ip[k]*wp[k];
    a += bias[n];
    o[idx] = relu ? fmaxf(a,0.f) : a;
}

// ---------------- launch ----------------
extern "C" void kernel_launch(void* const* d_in, const int* in_sizes, int n_in,
                              void* d_out, int out_size){
    const int*   seq  = (const int*)  d_in[0];
    const float* mask = (const float*)d_in[1];
    const float* aux  = (const float*)d_in[2];
    const float* emb  = (const float*)d_in[3];
    const float* Wih0 = (const float*)d_in[4];
    const float* Whh0 = (const float*)d_in[5];
    const float* b0   = (const float*)d_in[6];
    const float* WihL = (const float*)d_in[7];
    const float* WhhL = (const float*)d_in[8];
    const float* bLp  = (const float*)d_in[9];
    const float* gW   = (const float*)d_in[10];
    const float* gb   = (const float*)d_in[11];
    const float* gga  = (const float*)d_in[12];
    const float* gbe  = (const float*)d_in[13];
    const float* f1W  = (const float*)d_in[14];
    const float* f1b  = (const float*)d_in[15];
    const float* f2W  = (const float*)d_in[16];
    const float* f2b  = (const float*)d_in[17];
    const float* h0W  = (const float*)d_in[18];
    const float* h0b  = (const float*)d_in[19];
    const float* h1W  = (const float*)d_in[20];
    const float* h1b  = (const float*)d_in[21];
    float* out = (float*)d_out;

    float *pEMB,*pXA,*pXB,*pGT,*pT0,*pT1,*pP0,*pP1,*pFU,*pS1,*pS2;
    cudaGetSymbolAddress((void**)&pEMB,g_EMB);
    cudaGetSymbolAddress((void**)&pXA, g_XA);
    cudaGetSymbolAddress((void**)&pXB, g_XB);
    cudaGetSymbolAddress((void**)&pGT, g_GT);
    cudaGetSymbolAddress((void**)&pT0, g_T0);
    cudaGetSymbolAddress((void**)&pT1, g_T1);
    cudaGetSymbolAddress((void**)&pP0, g_P0);
    cudaGetSymbolAddress((void**)&pP1, g_P1);
    cudaGetSymbolAddress((void**)&pFU, g_FU);
    cudaGetSymbolAddress((void**)&pS1, g_S1);
    cudaGetSymbolAddress((void**)&pS2, g_S2);
    cudaFuncSetAttribute(k_lstm, cudaFuncAttributeMaxDynamicSharedMemorySize, LSM);

    k_embed<<<32768,64>>>(seq, emb);

    const float* inp = pEMB; int K = 256;
    float* lo = pXA;
    for(int l=0;l<5;l++){
        const float* wih = l ? WihL + (long)(l-1)*2*1024*512 : Wih0;
        const float* whh = l ? WhhL + (long)(l-1)*2*1024*256 : Whh0;
        const float* bb  = l ? bLp  + (long)(l-1)*2*1024      : b0;
        dim3 gg(2048/64, 32768/64);
        k_gemm<<<gg,256>>>(inp, wih, bb, pGT, K, 2048);
        lo = (l&1) ? pXB : pXA;
        k_lstm<<<128,256,LSM>>>(pGT, whh, whh + 1024*256, lo);
        inp = lo; K = 512;
    }
    const float* lstmOut = lo;

    const float* gin = pEMB;
    float* gout = pP0;
    for(int i=0;i<3;i++){
        k_band<<<32768,64>>>(gin, mask, pT0);
        dim3 gg(256/64, 32768/64);
        k_gemm<<<gg,256>>>(pT0, gW + (long)i*256*256, gb + i*256, pT1, 256, 256);
        gout = (i&1) ? pP1 : pP0;
        k_ln<<<32768,256>>>(pT1, gin, gga + i*256, gbe + i*256, gout);
        gin = gout;
    }

    k_pool<<<64,512>>>(lstmOut, gout, mask, aux);
    k_fc<<<(64*512+255)/256,256>>>(pFU, f1W, f1b, pS1, 774, 512, 1);
    k_fc<<<(64*256+255)/256,256>>>(pS1, f2W, f2b, pS2, 512, 256, 1);
    k_fc<<<(64*10+255)/256,256>>>(pS2, h0W, h0b, out,      256, 10, 0);
    k_fc<<<(64*5 +255)/256,256>>>(pS2, h1W, h1b, out+640, 256,  5, 0);
}